// round 3
// baseline (speedup 1.0000x reference)
#include <cuda_runtime.h>
#include <cstdint>

// Problem constants (match reference_code)
#define USER_NUM 1000000
#define EMBED_DIM 64
#define BATCH 16384

// FM scoring: out[e] = w[u] + w[i] + b + dot(V[u], V[i])
// (0.5*sum((Vu+Vi)^2 - Vu^2 - Vi^2) == sum(Vu*Vi))
//
// INPUT is int32 on the wire (JAX x64 disabled downgrades int64->int32).
//
// 16 lanes per group, 2 batch elements per group:
//  - one int4 load fetches both elements' (u,i) index pairs
//  - 4 float4 gathers + 4 broadcast w-loads + b issued back-to-back (MLP~9)
//  - dual shuffle reduction, one float2 store.
__global__ void __launch_bounds__(256) fm_score_kernel(
    const int*   __restrict__ inp,       // [BATCH, 2] int32
    const float* __restrict__ w,         // [USER_NUM + ITEM_NUM]
    const float* __restrict__ b,         // [1]
    const float* __restrict__ V,         // [USER_NUM + ITEM_NUM, 64]
    float*       __restrict__ out)       // [BATCH]
{
    const int gid   = blockIdx.x * blockDim.x + threadIdx.x;
    const int group = gid >> 4;          // handles elements 2*group, 2*group+1
    const int lane  = gid & 15;
    const int e0    = group * 2;
    if (e0 >= BATCH) return;

    // Indices for both elements in one 16B load (inp is 16B-aligned, 2 int per elem).
    const int4 idx = __ldg(reinterpret_cast<const int4*>(inp) + group);
    const long long u0 = (long long)idx.x;
    const long long i0 = (long long)idx.y + USER_NUM;
    const long long u1 = (long long)idx.z;
    const long long i1 = (long long)idx.w + USER_NUM;

    const float4* __restrict__ Vu0 = reinterpret_cast<const float4*>(V + u0 * EMBED_DIM);
    const float4* __restrict__ Vi0 = reinterpret_cast<const float4*>(V + i0 * EMBED_DIM);
    const float4* __restrict__ Vu1 = reinterpret_cast<const float4*>(V + u1 * EMBED_DIM);
    const float4* __restrict__ Vi1 = reinterpret_cast<const float4*>(V + i1 * EMBED_DIM);

    // Issue everything independent back-to-back: 4 gathers + 4 w + b.
    const float4 a0 = __ldg(&Vu0[lane]);
    const float4 c0 = __ldg(&Vi0[lane]);
    const float4 a1 = __ldg(&Vu1[lane]);
    const float4 c1 = __ldg(&Vi1[lane]);
    const float wu0 = __ldg(&w[u0]);   // same addr across group -> broadcast
    const float wi0 = __ldg(&w[i0]);
    const float wu1 = __ldg(&w[u1]);
    const float wi1 = __ldg(&w[i1]);
    const float bb  = __ldg(&b[0]);

    float dot0 = a0.x * c0.x + a0.y * c0.y + a0.z * c0.z + a0.w * c0.w;
    float dot1 = a1.x * c1.x + a1.y * c1.y + a1.z * c1.z + a1.w * c1.w;

    #pragma unroll
    for (int off = 8; off > 0; off >>= 1) {
        dot0 += __shfl_xor_sync(0xffffffffu, dot0, off);
        dot1 += __shfl_xor_sync(0xffffffffu, dot1, off);
    }

    if (lane == 0) {
        float2 r;
        r.x = wu0 + wi0 + bb + dot0;
        r.y = wu1 + wi1 + bb + dot1;
        *reinterpret_cast<float2*>(out + e0) = r;
    }
}

extern "C" void kernel_launch(void* const* d_in, const int* in_sizes, int n_in,
                              void* d_out, int out_size)
{
    const int*   inp = (const int*)d_in[0];    // INPUT int32 [BATCH,2]
    const float* w   = (const float*)d_in[1];  // w
    const float* b   = (const float*)d_in[2];  // b
    const float* V   = (const float*)d_in[3];  // V
    float*       out = (float*)d_out;          // [BATCH,1] float32

    const int threads = 256;
    const int total   = (BATCH / 2) * 16;      // 16 lanes per 2 elements
    const int blocks  = (total + threads - 1) / threads;
    fm_score_kernel<<<blocks, threads>>>(inp, w, b, V, out);
}